// round 7
// baseline (speedup 1.0000x reference)
#include <cuda_runtime.h>
#include <math.h>

// Problem constants
#define NB 8
#define NL 1024
#define NC 1024
#define NH 16
#define ND 64

// Scratch (device globals — no allocation allowed)
__device__ float g_q[NB*NH*NL*ND];   // [B,H,L,D]
__device__ float g_k[NB*NH*NL*ND];
__device__ float g_v[NB*NH*NL*ND];
__device__ float g_ao[NB*NL*NC];     // attention output, [B,L,C]

// ---------------- packed f32x2 helpers (FFMA2 path, sm_100+) ----------------
static __device__ __forceinline__ void fma2(unsigned long long &d,
                                            unsigned long long a,
                                            unsigned long long b) {
    asm("fma.rn.f32x2 %0, %1, %2, %0;" : "+l"(d) : "l"(a), "l"(b));
}
static __device__ __forceinline__ void mul2(unsigned long long &d,
                                            unsigned long long a,
                                            unsigned long long b) {
    asm("mul.rn.f32x2 %0, %1, %2;" : "=l"(d) : "l"(a), "l"(b));
}
static __device__ __forceinline__ void add2(unsigned long long &d,
                                            unsigned long long a,
                                            unsigned long long b) {
    asm("add.rn.f32x2 %0, %1, %2;" : "=l"(d) : "l"(a), "l"(b));
}
static __device__ __forceinline__ unsigned long long pack2(float x, float y) {
    unsigned long long r;
    asm("mov.b64 %0, {%1, %2};" : "=l"(r)
        : "r"(__float_as_uint(x)), "r"(__float_as_uint(y)));
    return r;
}
static __device__ __forceinline__ float2 unpack2(unsigned long long v) {
    unsigned int lo, hi;
    asm("mov.b64 {%0, %1}, %2;" : "=r"(lo), "=r"(hi) : "l"(v));
    return make_float2(__uint_as_float(lo), __uint_as_float(hi));
}

// ---------------- SGEMM core: C[128x128] tile of A[M,K] * B[N,K]^T ----------
// A row-major [M,K], Bw row-major [N,K] (i.e. NT gemm). 256 threads,
// 8x8 per-thread microtile, BK=16, f32x2 inner product.
__device__ __forceinline__ void gemm_tile(const float* __restrict__ A,
                                          const float* __restrict__ Bw,
                                          int m0, int n0, int K,
                                          float* As, float* Bs,
                                          unsigned long long acc[8][4]) {
    const int tid = threadIdx.x;
    const int tx = tid & 15;
    const int ty = tid >> 4;
    const int lr = tid >> 2;           // 0..63
    const int lc = (tid & 3) * 4;      // 0,4,8,12

    for (int kt = 0; kt < K; kt += 16) {
        __syncthreads();
        float4 a0 = *(const float4*)(A + (size_t)(m0 + lr)      * K + kt + lc);
        float4 a1 = *(const float4*)(A + (size_t)(m0 + lr + 64) * K + kt + lc);
        float4 b0 = *(const float4*)(Bw + (size_t)(n0 + lr)      * K + kt + lc);
        float4 b1 = *(const float4*)(Bw + (size_t)(n0 + lr + 64) * K + kt + lc);
        As[(lc+0)*128 + lr]      = a0.x; As[(lc+1)*128 + lr]      = a0.y;
        As[(lc+2)*128 + lr]      = a0.z; As[(lc+3)*128 + lr]      = a0.w;
        As[(lc+0)*128 + lr + 64] = a1.x; As[(lc+1)*128 + lr + 64] = a1.y;
        As[(lc+2)*128 + lr + 64] = a1.z; As[(lc+3)*128 + lr + 64] = a1.w;
        Bs[(lc+0)*128 + lr]      = b0.x; Bs[(lc+1)*128 + lr]      = b0.y;
        Bs[(lc+2)*128 + lr]      = b0.z; Bs[(lc+3)*128 + lr]      = b0.w;
        Bs[(lc+0)*128 + lr + 64] = b1.x; Bs[(lc+1)*128 + lr + 64] = b1.y;
        Bs[(lc+2)*128 + lr + 64] = b1.z; Bs[(lc+3)*128 + lr + 64] = b1.w;
        __syncthreads();

        #pragma unroll
        for (int k = 0; k < 16; k++) {
            const float4* Ar = (const float4*)(As + k * 128);
            float4 av0 = Ar[ty*2];
            float4 av1 = Ar[ty*2 + 1];
            const ulonglong2* Br = (const ulonglong2*)(Bs + k * 128);
            ulonglong2 bv0 = Br[tx*2];
            ulonglong2 bv1 = Br[tx*2 + 1];
            float a[8] = {av0.x, av0.y, av0.z, av0.w, av1.x, av1.y, av1.z, av1.w};
            #pragma unroll
            for (int i = 0; i < 8; i++) {
                unsigned long long aa = pack2(a[i], a[i]);
                fma2(acc[i][0], aa, bv0.x);
                fma2(acc[i][1], aa, bv0.y);
                fma2(acc[i][2], aa, bv1.x);
                fma2(acc[i][3], aa, bv1.y);
            }
        }
    }
}

// ---------------- Kernel 1: QKV GEMM + bias + scatter to [B,H,L,D] ----------
__global__ void __launch_bounds__(256)
k_qkv(const float* __restrict__ x, const float* __restrict__ w,
      const float* __restrict__ qb, const float* __restrict__ vb) {
    __shared__ float As[16 * 128];
    __shared__ float Bs[16 * 128];
    unsigned long long acc[8][4];
    #pragma unroll
    for (int i = 0; i < 8; i++)
        #pragma unroll
        for (int j = 0; j < 4; j++) acc[i][j] = 0ull;

    const int n0 = blockIdx.x * 128;
    const int m0 = blockIdx.y * 128;
    gemm_tile(x, w, m0, n0, NC, As, Bs, acc);

    const int tx = threadIdx.x & 15;
    const int ty = threadIdx.x >> 4;
    #pragma unroll
    for (int i = 0; i < 8; i++) {
        int m  = m0 + ty * 8 + i;
        int bb = m >> 10;
        int l  = m & 1023;
        #pragma unroll
        for (int g = 0; g < 2; g++) {
            int n     = n0 + tx * 8 + g * 4;
            int which = n >> 10;          // 0=q 1=k 2=v
            int cc    = n & 1023;
            int h     = cc >> 6;
            int dd    = cc & 63;
            union { unsigned long long u[2]; float4 f; } r;
            r.u[0] = acc[i][g*2];
            r.u[1] = acc[i][g*2 + 1];
            float* dst;
            if (which == 0) {
                float4 b4 = *(const float4*)(qb + cc);
                r.f.x += b4.x; r.f.y += b4.y; r.f.z += b4.z; r.f.w += b4.w;
                dst = g_q;
            } else if (which == 1) {
                dst = g_k;
            } else {
                float4 b4 = *(const float4*)(vb + cc);
                r.f.x += b4.x; r.f.y += b4.y; r.f.z += b4.z; r.f.w += b4.w;
                dst = g_v;
            }
            *(float4*)(dst + (((size_t)bb * NH + h) * NL + l) * ND + dd) = r.f;
        }
    }
}

// ---------------- Kernel 2: per-(b,h,l) L2 normalize of q (with scale) and k --
__global__ void k_norm(const float* __restrict__ scale_mul) {
    const int lane = threadIdx.x & 31;
    const int row  = blockIdx.x * (blockDim.x >> 5) + (threadIdx.x >> 5);
    const int NQ   = NB * NH * NL;
    const bool isq = row < NQ;
    const int r    = isq ? row : row - NQ;
    float* base = (isq ? g_q : g_k) + (size_t)r * ND;
    float2 v = ((float2*)base)[lane];
    float ss = v.x * v.x + v.y * v.y;
    #pragma unroll
    for (int m = 16; m >= 1; m >>= 1)
        ss += __shfl_xor_sync(0xffffffffu, ss, m);
    float mul = 1.0f;
    if (isq) {
        int h = (r >> 10) & 15;
        mul = __expf(fminf(scale_mul[h], 4.605170185988091f)); // log(100)
    }
    float sc = mul / fmaxf(sqrtf(ss), 1e-12f);
    v.x *= sc; v.y *= sc;
    ((float2*)base)[lane] = v;
}

// ---------------- Kernel 3: flash attention (fp32, online softmax) ----------
// Block = 128 threads, each owns one q row. 64-wide KV tiles.
__global__ void __launch_bounds__(128)
k_attn(const float* __restrict__ bias) {
    extern __shared__ float sm[];
    float* Ks  = sm;                  // 64*64
    float* Vs  = sm + 4096;           // 64*64
    float* Bsm = sm + 8192;           // 128*65 (padded)
    float* Ss  = sm + 8192 + 8320;    // 128*65 (padded)

    const int t  = threadIdx.x;       // q row within tile (0..127)
    const int bh = blockIdx.y;        // b*16 + h
    const int h  = bh & 15;
    const int q0 = blockIdx.x * 128;

    // Load this thread's q row into packed regs (32 x f32x2)
    unsigned long long q2[32];
    {
        const float4* qp = (const float4*)(g_q + ((size_t)bh * NL + q0 + t) * ND);
        #pragma unroll
        for (int c = 0; c < 16; c++) {
            union { float4 f; unsigned long long u[2]; } u;
            u.f = qp[c];
            q2[2*c] = u.u[0]; q2[2*c + 1] = u.u[1];
        }
    }
    unsigned long long o2[32];
    #pragma unroll
    for (int c = 0; c < 32; c++) o2[c] = 0ull;
    float mi = -INFINITY, li = 0.0f;

    for (int j0 = 0; j0 < NL; j0 += 64) {
        __syncthreads();  // previous tile fully consumed
        // K/V tiles: 1024 float4 each, coalesced
        {
            const float4* kp = (const float4*)(g_k + ((size_t)bh * NL + j0) * ND);
            const float4* vp = (const float4*)(g_v + ((size_t)bh * NL + j0) * ND);
            #pragma unroll
            for (int it = 0; it < 8; it++) {
                int idx = t + it * 128;
                ((float4*)Ks)[idx] = kp[idx];
                ((float4*)Vs)[idx] = vp[idx];
            }
            // bias tile: 128 rows x 64 cols, coalesced loads, padded stores
            const float* bb = bias + (size_t)h * NL * NL + (size_t)q0 * NL + j0;
            #pragma unroll
            for (int it = 0; it < 16; it++) {
                int idx = t + it * 128;       // 0..2047 over [128 rows][16 f4]
                int r = idx >> 4;
                int c = idx & 15;
                float4 bv = *(const float4*)(bb + (size_t)r * NL + c * 4);
                float* d = Bsm + r * 65 + c * 4;
                d[0] = bv.x; d[1] = bv.y; d[2] = bv.z; d[3] = bv.w;
            }
        }
        __syncthreads();

        // S = q . K^T + bias, tile max
        float tmax = -INFINITY;
        #pragma unroll 1
        for (int j = 0; j < 64; j++) {
            const ulonglong2* Kr = (const ulonglong2*)(Ks + j * 64);
            unsigned long long s0 = 0ull, s1 = 0ull, s2 = 0ull, s3 = 0ull;
            #pragma unroll
            for (int c = 0; c < 8; c++) {
                ulonglong2 kk0 = Kr[2*c];
                ulonglong2 kk1 = Kr[2*c + 1];
                fma2(s0, q2[4*c + 0], kk0.x);
                fma2(s1, q2[4*c + 1], kk0.y);
                fma2(s2, q2[4*c + 2], kk1.x);
                fma2(s3, q2[4*c + 3], kk1.y);
            }
            add2(s0, s0, s1);
            add2(s2, s2, s3);
            add2(s0, s0, s2);
            float2 sp = unpack2(s0);
            float s = sp.x + sp.y + Bsm[t * 65 + j];
            Ss[t * 65 + j] = s;
            tmax = fmaxf(tmax, s);
        }

        // online softmax rescale
        float mn    = fmaxf(mi, tmax);
        float alpha = __expf(mi - mn);     // first tile: exp(-inf)=0
        li *= alpha;
        unsigned long long a2 = pack2(alpha, alpha);
        #pragma unroll
        for (int c = 0; c < 32; c++) mul2(o2[c], o2[c], a2);
        mi = mn;

        // O += P * V
        #pragma unroll 1
        for (int j = 0; j < 64; j++) {
            float p = __expf(Ss[t * 65 + j] - mi);
            li += p;
            unsigned long long p2 = pack2(p, p);
            const ulonglong2* Vr = (const ulonglong2*)(Vs + j * 64);
            #pragma unroll
            for (int c = 0; c < 16; c++) {
                ulonglong2 vv = Vr[c];
                fma2(o2[2*c],     p2, vv.x);
                fma2(o2[2*c + 1], p2, vv.y);
            }
        }
    }

    // normalize and write to [B,L,C] layout
    float inv = 1.0f / li;
    unsigned long long i2 = pack2(inv, inv);
    float* op = g_ao + ((size_t)(bh >> 4) * NL + q0 + t) * NC + h * ND;
    #pragma unroll
    for (int c = 0; c < 16; c++) {
        unsigned long long lo = o2[2*c], hi = o2[2*c + 1];
        mul2(lo, lo, i2);
        mul2(hi, hi, i2);
        union { float4 f; unsigned long long u[2]; } u;
        u.u[0] = lo; u.u[1] = hi;
        ((float4*)op)[c] = u.f;
    }
}

// ---------------- Kernel 4: output projection GEMM + bias -------------------
__global__ void __launch_bounds__(256)
k_proj(const float* __restrict__ w, const float* __restrict__ bp,
       float* __restrict__ out) {
    __shared__ float As[16 * 128];
    __shared__ float Bs[16 * 128];
    unsigned long long acc[8][4];
    #pragma unroll
    for (int i = 0; i < 8; i++)
        #pragma unroll
        for (int j = 0; j < 4; j++) acc[i][j] = 0ull;

    const int n0 = blockIdx.x * 128;
    const int m0 = blockIdx.y * 128;
    gemm_tile(g_ao, w, m0, n0, NC, As, Bs, acc);

    const int tx = threadIdx.x & 15;
    const int ty = threadIdx.x >> 4;
    #pragma unroll
    for (int i = 0; i < 8; i++) {
        int m = m0 + ty * 8 + i;
        #pragma unroll
        for (int g = 0; g < 2; g++) {
            int n = n0 + tx * 8 + g * 4;
            union { unsigned long long u[2]; float4 f; } r;
            r.u[0] = acc[i][g*2];
            r.u[1] = acc[i][g*2 + 1];
            float4 b4 = *(const float4*)(bp + n);
            r.f.x += b4.x; r.f.y += b4.y; r.f.z += b4.z; r.f.w += b4.w;
            *(float4*)(out + (size_t)m * NC + n) = r.f;
        }
    }
}

// ---------------- host launcher ---------------------------------------------
extern "C" void kernel_launch(void* const* d_in, const int* in_sizes, int n_in,
                              void* d_out, int out_size) {
    const float* x         = (const float*)d_in[0];
    const float* attn_bias = (const float*)d_in[1];
    const float* w_qkv     = (const float*)d_in[2];
    const float* q_bias    = (const float*)d_in[3];
    const float* v_bias    = (const float*)d_in[4];
    const float* scale_mul = (const float*)d_in[5];
    const float* w_proj    = (const float*)d_in[6];
    const float* b_proj    = (const float*)d_in[7];
    float* out = (float*)d_out;

    // QKV projection: [8192,1024] x [3072,1024]^T
    k_qkv<<<dim3(24, 64), 256>>>(x, w_qkv, q_bias, v_bias);

    // L2-normalize q (with exp(min(scale,log100)) scale) and k
    k_norm<<<32768, 256>>>(scale_mul);

    // attention: 8 q-tiles x 128 (b,h) blocks; 99328 B dynamic smem
    cudaFuncSetAttribute(k_attn, cudaFuncAttributeMaxDynamicSharedMemorySize, 99328);
    k_attn<<<dim3(8, 128), 128, 99328>>>(attn_bias);

    // output projection: [8192,1024] x [1024,1024]^T
    k_proj<<<dim3(8, 64), 256>>>(w_proj, b_proj, out);
}

// round 8
// speedup vs baseline: 1.5258x; 1.5258x over previous
#include <cuda_runtime.h>
#include <math.h>

// Problem constants
#define NB 8
#define NL 1024
#define NC 1024
#define NH 16
#define ND 64

// Scratch (device globals — no allocation allowed)
__device__ float g_q[NB*NH*NL*ND];   // [B,H,L,D]
__device__ float g_k[NB*NH*NL*ND];
__device__ float g_v[NB*NH*NL*ND];
__device__ float g_ao[NB*NL*NC];     // attention output, [B,L,C]

// ---------------- packed f32x2 helpers (FFMA2 path, sm_100+) ----------------
static __device__ __forceinline__ void fma2(unsigned long long &d,
                                            unsigned long long a,
                                            unsigned long long b) {
    asm("fma.rn.f32x2 %0, %1, %2, %0;" : "+l"(d) : "l"(a), "l"(b));
}
static __device__ __forceinline__ void mul2(unsigned long long &d,
                                            unsigned long long a,
                                            unsigned long long b) {
    asm("mul.rn.f32x2 %0, %1, %2;" : "=l"(d) : "l"(a), "l"(b));
}
static __device__ __forceinline__ void add2(unsigned long long &d,
                                            unsigned long long a,
                                            unsigned long long b) {
    asm("add.rn.f32x2 %0, %1, %2;" : "=l"(d) : "l"(a), "l"(b));
}
static __device__ __forceinline__ unsigned long long pack2(float x, float y) {
    unsigned long long r;
    asm("mov.b64 %0, {%1, %2};" : "=l"(r)
        : "r"(__float_as_uint(x)), "r"(__float_as_uint(y)));
    return r;
}
static __device__ __forceinline__ float2 unpack2(unsigned long long v) {
    unsigned int lo, hi;
    asm("mov.b64 {%0, %1}, %2;" : "=r"(lo), "=r"(hi) : "l"(v));
    return make_float2(__uint_as_float(lo), __uint_as_float(hi));
}

// ---------------- TF32 tensor-core helpers ----------------------------------
static __device__ __forceinline__ unsigned f2tf(float f) {
    unsigned r;
    asm("cvt.rna.tf32.f32 %0, %1;" : "=r"(r) : "f"(f));
    return r;
}
static __device__ __forceinline__ void mma_tf32(float c[4], const unsigned a[4],
                                                const unsigned b[2]) {
    asm("mma.sync.aligned.m16n8k8.row.col.f32.tf32.tf32.f32 "
        "{%0,%1,%2,%3}, {%4,%5,%6,%7}, {%8,%9}, {%0,%1,%2,%3};"
        : "+f"(c[0]), "+f"(c[1]), "+f"(c[2]), "+f"(c[3])
        : "r"(a[0]), "r"(a[1]), "r"(a[2]), "r"(a[3]), "r"(b[0]), "r"(b[1]));
}

// ---------------- TF32 NT GEMM core: 128x128 C-tile of A[M,K] * B[N,K]^T ----
// 256 threads = 8 warps arranged 4(M) x 2(N); warp tile 32x64.
// Smem pitch 36 floats -> fragment loads are bank-conflict-free (4m+k).
#define GPITCH 36
#define SM_BUF 4608                 // 128*36 words per tile buffer

__device__ __forceinline__ void gemm_tf32(const float* __restrict__ A,
                                          const float* __restrict__ Bw,
                                          int m0, int n0, int K,
                                          unsigned* sm, float acc[2][8][4]) {
    const int tid  = threadIdx.x;
    const int lane = tid & 31, wid = tid >> 5;
    const int wm = (wid & 3) << 5;           // warp m offset
    const int wn = (wid >> 2) << 6;          // warp n offset
    const int g  = lane >> 2, tg = lane & 3; // mma groupID / threadInGroup
    const int r0 = tid >> 3, slot = tid & 7; // loader: row base, float4 slot

    unsigned* sA[2] = { sm,              sm + SM_BUF };
    unsigned* sB[2] = { sm + 2 * SM_BUF, sm + 3 * SM_BUF };

    const float* pA = A  + (size_t)(m0 + r0) * K + slot * 4;
    const float* pB = Bw + (size_t)(n0 + r0) * K + slot * 4;

    float4 a4[4], b4[4];
    // prologue: tile 0 -> buf 0
    #pragma unroll
    for (int i = 0; i < 4; i++) {
        a4[i] = *(const float4*)(pA + (size_t)(i * 32) * K);
        b4[i] = *(const float4*)(pB + (size_t)(i * 32) * K);
    }
    #pragma unroll
    for (int i = 0; i < 4; i++) {
        uint4 ua = make_uint4(f2tf(a4[i].x), f2tf(a4[i].y), f2tf(a4[i].z), f2tf(a4[i].w));
        uint4 ub = make_uint4(f2tf(b4[i].x), f2tf(b4[i].y), f2tf(b4[i].z), f2tf(b4[i].w));
        *(uint4*)(sA[0] + (r0 + i * 32) * GPITCH + slot * 4) = ua;
        *(uint4*)(sB[0] + (r0 + i * 32) * GPITCH + slot * 4) = ub;
    }
    __syncthreads();

    const int NT = K >> 5;                   // BK = 32
    for (int kt = 0; kt < NT; kt++) {
        const int cur = kt & 1;
        if (kt + 1 < NT) {
            const float* qA = pA + (kt + 1) * 32;
            const float* qB = pB + (kt + 1) * 32;
            #pragma unroll
            for (int i = 0; i < 4; i++) {
                a4[i] = *(const float4*)(qA + (size_t)(i * 32) * K);
                b4[i] = *(const float4*)(qB + (size_t)(i * 32) * K);
            }
        }
        const unsigned* cA = sA[cur];
        const unsigned* cB = sB[cur];
        #pragma unroll
        for (int ks = 0; ks < 4; ks++) {
            const int k0 = ks * 8;
            unsigned af[2][4], bf[8][2];
            #pragma unroll
            for (int mt = 0; mt < 2; mt++) {
                const unsigned* p = cA + (wm + mt * 16 + g) * GPITCH + k0 + tg;
                af[mt][0] = p[0];
                af[mt][1] = p[8 * GPITCH];
                af[mt][2] = p[4];
                af[mt][3] = p[8 * GPITCH + 4];
            }
            #pragma unroll
            for (int nt = 0; nt < 8; nt++) {
                const unsigned* p = cB + (wn + nt * 8 + g) * GPITCH + k0 + tg;
                bf[nt][0] = p[0];
                bf[nt][1] = p[4];
            }
            #pragma unroll
            for (int mt = 0; mt < 2; mt++)
                #pragma unroll
                for (int nt = 0; nt < 8; nt++)
                    mma_tf32(acc[mt][nt], af[mt], bf[nt]);
        }
        if (kt + 1 < NT) {
            const int nxt = cur ^ 1;
            #pragma unroll
            for (int i = 0; i < 4; i++) {
                uint4 ua = make_uint4(f2tf(a4[i].x), f2tf(a4[i].y), f2tf(a4[i].z), f2tf(a4[i].w));
                uint4 ub = make_uint4(f2tf(b4[i].x), f2tf(b4[i].y), f2tf(b4[i].z), f2tf(b4[i].w));
                *(uint4*)(sA[nxt] + (r0 + i * 32) * GPITCH + slot * 4) = ua;
                *(uint4*)(sB[nxt] + (r0 + i * 32) * GPITCH + slot * 4) = ub;
            }
        }
        __syncthreads();
    }
}

// ---------------- Kernel 1: QKV GEMM (TF32) + bias + scatter to [B,H,L,D] ---
__global__ void __launch_bounds__(256)
k_qkv(const float* __restrict__ x, const float* __restrict__ w,
      const float* __restrict__ qb, const float* __restrict__ vb) {
    extern __shared__ unsigned smemu[];
    float acc[2][8][4];
    #pragma unroll
    for (int i = 0; i < 2; i++)
        #pragma unroll
        for (int j = 0; j < 8; j++)
            #pragma unroll
            for (int r = 0; r < 4; r++) acc[i][j][r] = 0.0f;

    const int n0 = blockIdx.x * 128;
    const int m0 = blockIdx.y * 128;
    gemm_tf32(x, w, m0, n0, NC, smemu, acc);

    const int lane = threadIdx.x & 31, wid = threadIdx.x >> 5;
    const int wm = (wid & 3) << 5, wn = (wid >> 2) << 6;
    const int g = lane >> 2, tg = lane & 3;

    #pragma unroll
    for (int mt = 0; mt < 2; mt++) {
        #pragma unroll
        for (int half = 0; half < 2; half++) {
            int m  = m0 + wm + mt * 16 + g + half * 8;
            int bb = m >> 10;
            int l  = m & 1023;
            #pragma unroll
            for (int nt = 0; nt < 8; nt++) {
                int n     = n0 + wn + nt * 8 + 2 * tg;
                int which = n >> 10;           // 0=q 1=k 2=v
                int cc    = n & 1023;
                int h     = cc >> 6;
                int dd    = cc & 63;
                float2 r;
                r.x = acc[mt][nt][half * 2 + 0];
                r.y = acc[mt][nt][half * 2 + 1];
                float* dst;
                if (which == 0) {
                    float2 b2 = *(const float2*)(qb + cc);
                    r.x += b2.x; r.y += b2.y;
                    dst = g_q;
                } else if (which == 1) {
                    dst = g_k;
                } else {
                    float2 b2 = *(const float2*)(vb + cc);
                    r.x += b2.x; r.y += b2.y;
                    dst = g_v;
                }
                *(float2*)(dst + (((size_t)bb * NH + h) * NL + l) * ND + dd) = r;
            }
        }
    }
}

// ---------------- Kernel 2: per-(b,h,l) L2 normalize of q (scaled) and k ----
__global__ void k_norm(const float* __restrict__ scale_mul) {
    const int lane = threadIdx.x & 31;
    const int row  = blockIdx.x * (blockDim.x >> 5) + (threadIdx.x >> 5);
    const int NQ   = NB * NH * NL;
    const bool isq = row < NQ;
    const int r    = isq ? row : row - NQ;
    float* base = (isq ? g_q : g_k) + (size_t)r * ND;
    float2 v = ((float2*)base)[lane];
    float ss = v.x * v.x + v.y * v.y;
    #pragma unroll
    for (int m = 16; m >= 1; m >>= 1)
        ss += __shfl_xor_sync(0xffffffffu, ss, m);
    float mul = 1.0f;
    if (isq) {
        int h = (r >> 10) & 15;
        mul = __expf(fminf(scale_mul[h], 4.605170185988091f)); // log(100)
    }
    float sc = mul / fmaxf(sqrtf(ss), 1e-12f);
    v.x *= sc; v.y *= sc;
    ((float2*)base)[lane] = v;
}

// ---------------- Kernel 3: flash attention (fp32, online softmax) ----------
// Block = 128 threads, each owns one q row. 64-wide KV tiles.
__global__ void __launch_bounds__(128)
k_attn(const float* __restrict__ bias) {
    extern __shared__ float sm[];
    float* Ks  = sm;                  // 64*64
    float* Vs  = sm + 4096;           // 64*64
    float* Bsm = sm + 8192;           // 128*65 (padded)
    float* Ss  = sm + 8192 + 8320;    // 128*65 (padded)

    const int t  = threadIdx.x;       // q row within tile (0..127)
    const int bh = blockIdx.y;        // b*16 + h
    const int h  = bh & 15;
    const int q0 = blockIdx.x * 128;

    // Load this thread's q row into packed regs (32 x f32x2)
    unsigned long long q2[32];
    {
        const float4* qp = (const float4*)(g_q + ((size_t)bh * NL + q0 + t) * ND);
        #pragma unroll
        for (int c = 0; c < 16; c++) {
            union { float4 f; unsigned long long u[2]; } u;
            u.f = qp[c];
            q2[2*c] = u.u[0]; q2[2*c + 1] = u.u[1];
        }
    }
    unsigned long long o2[32];
    #pragma unroll
    for (int c = 0; c < 32; c++) o2[c] = 0ull;
    float mi = -INFINITY, li = 0.0f;

    for (int j0 = 0; j0 < NL; j0 += 64) {
        __syncthreads();  // previous tile fully consumed
        // K/V tiles: 1024 float4 each, coalesced
        {
            const float4* kp = (const float4*)(g_k + ((size_t)bh * NL + j0) * ND);
            const float4* vp = (const float4*)(g_v + ((size_t)bh * NL + j0) * ND);
            #pragma unroll
            for (int it = 0; it < 8; it++) {
                int idx = t + it * 128;
                ((float4*)Ks)[idx] = kp[idx];
                ((float4*)Vs)[idx] = vp[idx];
            }
            // bias tile: 128 rows x 64 cols, coalesced loads, padded stores
            const float* bb = bias + (size_t)h * NL * NL + (size_t)q0 * NL + j0;
            #pragma unroll
            for (int it = 0; it < 16; it++) {
                int idx = t + it * 128;       // 0..2047 over [128 rows][16 f4]
                int r = idx >> 4;
                int c = idx & 15;
                float4 bv = *(const float4*)(bb + (size_t)r * NL + c * 4);
                float* d = Bsm + r * 65 + c * 4;
                d[0] = bv.x; d[1] = bv.y; d[2] = bv.z; d[3] = bv.w;
            }
        }
        __syncthreads();

        // S = q . K^T + bias, tile max
        float tmax = -INFINITY;
        #pragma unroll 1
        for (int j = 0; j < 64; j++) {
            const ulonglong2* Kr = (const ulonglong2*)(Ks + j * 64);
            unsigned long long s0 = 0ull, s1 = 0ull, s2 = 0ull, s3 = 0ull;
            #pragma unroll
            for (int c = 0; c < 8; c++) {
                ulonglong2 kk0 = Kr[2*c];
                ulonglong2 kk1 = Kr[2*c + 1];
                fma2(s0, q2[4*c + 0], kk0.x);
                fma2(s1, q2[4*c + 1], kk0.y);
                fma2(s2, q2[4*c + 2], kk1.x);
                fma2(s3, q2[4*c + 3], kk1.y);
            }
            add2(s0, s0, s1);
            add2(s2, s2, s3);
            add2(s0, s0, s2);
            float2 sp = unpack2(s0);
            float s = sp.x + sp.y + Bsm[t * 65 + j];
            Ss[t * 65 + j] = s;
            tmax = fmaxf(tmax, s);
        }

        // online softmax rescale
        float mn    = fmaxf(mi, tmax);
        float alpha = __expf(mi - mn);     // first tile: exp(-inf)=0
        li *= alpha;
        unsigned long long a2 = pack2(alpha, alpha);
        #pragma unroll
        for (int c = 0; c < 32; c++) mul2(o2[c], o2[c], a2);
        mi = mn;

        // O += P * V
        #pragma unroll 1
        for (int j = 0; j < 64; j++) {
            float p = __expf(Ss[t * 65 + j] - mi);
            li += p;
            unsigned long long p2 = pack2(p, p);
            const ulonglong2* Vr = (const ulonglong2*)(Vs + j * 64);
            #pragma unroll
            for (int c = 0; c < 16; c++) {
                ulonglong2 vv = Vr[c];
                fma2(o2[2*c],     p2, vv.x);
                fma2(o2[2*c + 1], p2, vv.y);
            }
        }
    }

    // normalize and write to [B,L,C] layout
    float inv = 1.0f / li;
    unsigned long long i2 = pack2(inv, inv);
    float* op = g_ao + ((size_t)(bh >> 4) * NL + q0 + t) * NC + h * ND;
    #pragma unroll
    for (int c = 0; c < 16; c++) {
        unsigned long long lo = o2[2*c], hi = o2[2*c + 1];
        mul2(lo, lo, i2);
        mul2(hi, hi, i2);
        union { float4 f; unsigned long long u[2]; } u;
        u.u[0] = lo; u.u[1] = hi;
        ((float4*)op)[c] = u.f;
    }
}

// ---------------- Kernel 4: output projection GEMM (TF32) + bias ------------
__global__ void __launch_bounds__(256)
k_proj(const float* __restrict__ w, const float* __restrict__ bp,
       float* __restrict__ out) {
    extern __shared__ unsigned smemu[];
    float acc[2][8][4];
    #pragma unroll
    for (int i = 0; i < 2; i++)
        #pragma unroll
        for (int j = 0; j < 8; j++)
            #pragma unroll
            for (int r = 0; r < 4; r++) acc[i][j][r] = 0.0f;

    const int n0 = blockIdx.x * 128;
    const int m0 = blockIdx.y * 128;
    gemm_tf32(g_ao, w, m0, n0, NC, smemu, acc);

    const int lane = threadIdx.x & 31, wid = threadIdx.x >> 5;
    const int wm = (wid & 3) << 5, wn = (wid >> 2) << 6;
    const int g = lane >> 2, tg = lane & 3;

    #pragma unroll
    for (int mt = 0; mt < 2; mt++) {
        #pragma unroll
        for (int half = 0; half < 2; half++) {
            int m = m0 + wm + mt * 16 + g + half * 8;
            #pragma unroll
            for (int nt = 0; nt < 8; nt++) {
                int n = n0 + wn + nt * 8 + 2 * tg;
                float2 b2 = *(const float2*)(bp + n);
                float2 r;
                r.x = acc[mt][nt][half * 2 + 0] + b2.x;
                r.y = acc[mt][nt][half * 2 + 1] + b2.y;
                *(float2*)(out + (size_t)m * NC + n) = r;
            }
        }
    }
}

// ---------------- host launcher ---------------------------------------------
extern "C" void kernel_launch(void* const* d_in, const int* in_sizes, int n_in,
                              void* d_out, int out_size) {
    const float* x         = (const float*)d_in[0];
    const float* attn_bias = (const float*)d_in[1];
    const float* w_qkv     = (const float*)d_in[2];
    const float* q_bias    = (const float*)d_in[3];
    const float* v_bias    = (const float*)d_in[4];
    const float* scale_mul = (const float*)d_in[5];
    const float* w_proj    = (const float*)d_in[6];
    const float* b_proj    = (const float*)d_in[7];
    float* out = (float*)d_out;

    const int GEMM_SMEM = 4 * SM_BUF * 4;   // 73728 B (double-buffered A+B)
    cudaFuncSetAttribute(k_qkv,  cudaFuncAttributeMaxDynamicSharedMemorySize, GEMM_SMEM);
    cudaFuncSetAttribute(k_proj, cudaFuncAttributeMaxDynamicSharedMemorySize, GEMM_SMEM);

    // QKV projection: [8192,1024] x [3072,1024]^T (TF32 tensor cores)
    k_qkv<<<dim3(24, 64), 256, GEMM_SMEM>>>(x, w_qkv, q_bias, v_bias);

    // L2-normalize q (with exp(min(scale,log100)) scale) and k
    k_norm<<<32768, 256>>>(scale_mul);

    // attention: 8 q-tiles x 128 (b,h) blocks; 99328 B dynamic smem
    cudaFuncSetAttribute(k_attn, cudaFuncAttributeMaxDynamicSharedMemorySize, 99328);
    k_attn<<<dim3(8, 128), 128, 99328>>>(attn_bias);

    // output projection: [8192,1024] x [1024,1024]^T (TF32 tensor cores)
    k_proj<<<dim3(8, 64), 256, GEMM_SMEM>>>(w_proj, b_proj, out);
}

// round 9
// speedup vs baseline: 2.5736x; 1.6867x over previous
#include <cuda_runtime.h>
#include <math.h>

// Problem constants
#define NB 8
#define NL 1024
#define NC 1024
#define NH 16
#define ND 64

// Scratch (device globals — no allocation allowed)
__device__ float g_q[NB*NH*NL*ND];   // [B,H,L,D]
__device__ float g_k[NB*NH*NL*ND];
__device__ float g_v[NB*NH*NL*ND];
__device__ float g_ao[NB*NL*NC];     // attention output, [B,L,C]

// ---------------- TF32 tensor-core helpers ----------------------------------
static __device__ __forceinline__ unsigned f2tf(float f) {
    unsigned r;
    asm("cvt.rna.tf32.f32 %0, %1;" : "=r"(r) : "f"(f));
    return r;
}
static __device__ __forceinline__ void mma_tf32(float c[4], const unsigned a[4],
                                                const unsigned b[2]) {
    asm("mma.sync.aligned.m16n8k8.row.col.f32.tf32.tf32.f32 "
        "{%0,%1,%2,%3}, {%4,%5,%6,%7}, {%8,%9}, {%0,%1,%2,%3};"
        : "+f"(c[0]), "+f"(c[1]), "+f"(c[2]), "+f"(c[3])
        : "r"(a[0]), "r"(a[1]), "r"(a[2]), "r"(a[3]), "r"(b[0]), "r"(b[1]));
}

// ---------------- TF32 NT GEMM core: 128x128 C-tile of A[M,K] * B[N,K]^T ----
// 256 threads = 8 warps arranged 4(M) x 2(N); warp tile 32x64.
// Smem pitch 36 floats -> fragment loads are bank-conflict-free (4m+k).
#define GPITCH 36
#define SM_BUF 4608                 // 128*36 words per tile buffer

__device__ __forceinline__ void gemm_tf32(const float* __restrict__ A,
                                          const float* __restrict__ Bw,
                                          int m0, int n0, int K,
                                          unsigned* sm, float acc[2][8][4]) {
    const int tid  = threadIdx.x;
    const int lane = tid & 31, wid = tid >> 5;
    const int wm = (wid & 3) << 5;           // warp m offset
    const int wn = (wid >> 2) << 6;          // warp n offset
    const int g  = lane >> 2, tg = lane & 3; // mma groupID / threadInGroup
    const int r0 = tid >> 3, slot = tid & 7; // loader: row base, float4 slot

    unsigned* sA[2] = { sm,              sm + SM_BUF };
    unsigned* sB[2] = { sm + 2 * SM_BUF, sm + 3 * SM_BUF };

    const float* pA = A  + (size_t)(m0 + r0) * K + slot * 4;
    const float* pB = Bw + (size_t)(n0 + r0) * K + slot * 4;

    float4 a4[4], b4[4];
    // prologue: tile 0 -> buf 0
    #pragma unroll
    for (int i = 0; i < 4; i++) {
        a4[i] = *(const float4*)(pA + (size_t)(i * 32) * K);
        b4[i] = *(const float4*)(pB + (size_t)(i * 32) * K);
    }
    #pragma unroll
    for (int i = 0; i < 4; i++) {
        uint4 ua = make_uint4(f2tf(a4[i].x), f2tf(a4[i].y), f2tf(a4[i].z), f2tf(a4[i].w));
        uint4 ub = make_uint4(f2tf(b4[i].x), f2tf(b4[i].y), f2tf(b4[i].z), f2tf(b4[i].w));
        *(uint4*)(sA[0] + (r0 + i * 32) * GPITCH + slot * 4) = ua;
        *(uint4*)(sB[0] + (r0 + i * 32) * GPITCH + slot * 4) = ub;
    }
    __syncthreads();

    const int NT = K >> 5;                   // BK = 32
    for (int kt = 0; kt < NT; kt++) {
        const int cur = kt & 1;
        if (kt + 1 < NT) {
            const float* qA = pA + (kt + 1) * 32;
            const float* qB = pB + (kt + 1) * 32;
            #pragma unroll
            for (int i = 0; i < 4; i++) {
                a4[i] = *(const float4*)(qA + (size_t)(i * 32) * K);
                b4[i] = *(const float4*)(qB + (size_t)(i * 32) * K);
            }
        }
        const unsigned* cA = sA[cur];
        const unsigned* cB = sB[cur];
        #pragma unroll
        for (int ks = 0; ks < 4; ks++) {
            const int k0 = ks * 8;
            unsigned af[2][4], bf[8][2];
            #pragma unroll
            for (int mt = 0; mt < 2; mt++) {
                const unsigned* p = cA + (wm + mt * 16 + g) * GPITCH + k0 + tg;
                af[mt][0] = p[0];
                af[mt][1] = p[8 * GPITCH];
                af[mt][2] = p[4];
                af[mt][3] = p[8 * GPITCH + 4];
            }
            #pragma unroll
            for (int nt = 0; nt < 8; nt++) {
                const unsigned* p = cB + (wn + nt * 8 + g) * GPITCH + k0 + tg;
                bf[nt][0] = p[0];
                bf[nt][1] = p[4];
            }
            #pragma unroll
            for (int mt = 0; mt < 2; mt++)
                #pragma unroll
                for (int nt = 0; nt < 8; nt++)
                    mma_tf32(acc[mt][nt], af[mt], bf[nt]);
        }
        if (kt + 1 < NT) {
            const int nxt = cur ^ 1;
            #pragma unroll
            for (int i = 0; i < 4; i++) {
                uint4 ua = make_uint4(f2tf(a4[i].x), f2tf(a4[i].y), f2tf(a4[i].z), f2tf(a4[i].w));
                uint4 ub = make_uint4(f2tf(b4[i].x), f2tf(b4[i].y), f2tf(b4[i].z), f2tf(b4[i].w));
                *(uint4*)(sA[nxt] + (r0 + i * 32) * GPITCH + slot * 4) = ua;
                *(uint4*)(sB[nxt] + (r0 + i * 32) * GPITCH + slot * 4) = ub;
            }
        }
        __syncthreads();
    }
}

// ---------------- Kernel 1: QKV GEMM (TF32) + bias + scatter to [B,H,L,D] ---
__global__ void __launch_bounds__(256)
k_qkv(const float* __restrict__ x, const float* __restrict__ w,
      const float* __restrict__ qb, const float* __restrict__ vb) {
    extern __shared__ unsigned smemu[];
    float acc[2][8][4];
    #pragma unroll
    for (int i = 0; i < 2; i++)
        #pragma unroll
        for (int j = 0; j < 8; j++)
            #pragma unroll
            for (int r = 0; r < 4; r++) acc[i][j][r] = 0.0f;

    const int n0 = blockIdx.x * 128;
    const int m0 = blockIdx.y * 128;
    gemm_tf32(x, w, m0, n0, NC, smemu, acc);

    const int lane = threadIdx.x & 31, wid = threadIdx.x >> 5;
    const int wm = (wid & 3) << 5, wn = (wid >> 2) << 6;
    const int g = lane >> 2, tg = lane & 3;

    #pragma unroll
    for (int mt = 0; mt < 2; mt++) {
        #pragma unroll
        for (int half = 0; half < 2; half++) {
            int m  = m0 + wm + mt * 16 + g + half * 8;
            int bb = m >> 10;
            int l  = m & 1023;
            #pragma unroll
            for (int nt = 0; nt < 8; nt++) {
                int n     = n0 + wn + nt * 8 + 2 * tg;
                int which = n >> 10;           // 0=q 1=k 2=v
                int cc    = n & 1023;
                int h     = cc >> 6;
                int dd    = cc & 63;
                float2 r;
                r.x = acc[mt][nt][half * 2 + 0];
                r.y = acc[mt][nt][half * 2 + 1];
                float* dst;
                if (which == 0) {
                    float2 b2 = *(const float2*)(qb + cc);
                    r.x += b2.x; r.y += b2.y;
                    dst = g_q;
                } else if (which == 1) {
                    dst = g_k;
                } else {
                    float2 b2 = *(const float2*)(vb + cc);
                    r.x += b2.x; r.y += b2.y;
                    dst = g_v;
                }
                *(float2*)(dst + (((size_t)bb * NH + h) * NL + l) * ND + dd) = r;
            }
        }
    }
}

// ---------------- Kernel 2: per-(b,h,l) L2 normalize of q (scaled) and k ----
__global__ void k_norm(const float* __restrict__ scale_mul) {
    const int lane = threadIdx.x & 31;
    const int row  = blockIdx.x * (blockDim.x >> 5) + (threadIdx.x >> 5);
    const int NQ   = NB * NH * NL;
    const bool isq = row < NQ;
    const int r    = isq ? row : row - NQ;
    float* base = (isq ? g_q : g_k) + (size_t)r * ND;
    float2 v = ((float2*)base)[lane];
    float ss = v.x * v.x + v.y * v.y;
    #pragma unroll
    for (int m = 16; m >= 1; m >>= 1)
        ss += __shfl_xor_sync(0xffffffffu, ss, m);
    float mul = 1.0f;
    if (isq) {
        int h = (r >> 10) & 15;
        mul = __expf(fminf(scale_mul[h], 4.605170185988091f)); // log(100)
    }
    float sc = mul / fmaxf(sqrtf(ss), 1e-12f);
    v.x *= sc; v.y *= sc;
    ((float2*)base)[lane] = v;
}

// ---------------- Kernel 3: flash attention (TF32 tensor cores) -------------
// Block = 128 threads (4 warps). Each warp owns 16 q rows; 64-wide KV tiles.
// QK^T uses 3xTF32 split (near-fp32); PV single TF32.
#define AP 68                      // smem pitch: (4g+tg) covers all 32 banks

__global__ void __launch_bounds__(128)
k_attn(const float* __restrict__ bias) {
    extern __shared__ unsigned smu[];
    unsigned* Kh = smu;            // [64][AP] tf32(K)
    unsigned* Kl = smu + 64 * AP;  // [64][AP] tf32(K - tf32(K))
    unsigned* Vt = smu + 2 * 64 * AP;  // [d][kv] transposed tf32(V)
    unsigned* Ps = smu + 3 * 64 * AP;  // [64 rows][AP] tf32(P)

    const int t    = threadIdx.x;
    const int lane = t & 31, w = t >> 5;
    const int g = lane >> 2, tg = lane & 3;
    const int bh = blockIdx.y, h = bh & 15;
    const int q0 = blockIdx.x * 64;
    const int r0 = w * 16 + g;        // block-local q row (this thread: r0, r0+8)

    // Q fragments, hi/lo split, resident for the whole loop
    unsigned qh[8][4], ql[8][4];
    {
        const float* qbase = g_q + ((size_t)bh * NL + q0) * ND;
        #pragma unroll
        for (int kg = 0; kg < 8; kg++) {
            #pragma unroll
            for (int i = 0; i < 4; i++) {
                int row = r0 + (i & 1) * 8;
                int kk  = kg * 8 + tg + (i >> 1) * 4;
                float x = qbase[(size_t)row * ND + kk];
                unsigned xh = f2tf(x);
                qh[kg][i] = xh;
                ql[kg][i] = f2tf(x - __uint_as_float(xh));
            }
        }
    }

    float o[8][4];
    #pragma unroll
    for (int nt = 0; nt < 8; nt++)
        #pragma unroll
        for (int i = 0; i < 4; i++) o[nt][i] = 0.0f;
    float m0 = -INFINITY, m1 = -INFINITY, l0 = 0.0f, l1 = 0.0f;
    const float* bb = bias + (size_t)h * NL * NL;

    for (int j0 = 0; j0 < NL; j0 += 64) {
        __syncthreads();              // previous tile fully consumed
        // Load K tile (split hi/lo) and V tile (transposed), convert to tf32
        {
            const float* kp = g_k + ((size_t)bh * NL + j0) * ND;
            const float* vp = g_v + ((size_t)bh * NL + j0) * ND;
            #pragma unroll
            for (int it = 0; it < 8; it++) {
                int idx = t + it * 128;          // 1024 float4 slots
                int row = idx >> 4, c4 = (idx & 15) * 4;
                float4 k4 = *(const float4*)(kp + (size_t)row * ND + c4);
                float4 v4 = *(const float4*)(vp + (size_t)row * ND + c4);
                float kf[4] = {k4.x, k4.y, k4.z, k4.w};
                float vf[4] = {v4.x, v4.y, v4.z, v4.w};
                #pragma unroll
                for (int i = 0; i < 4; i++) {
                    unsigned xh = f2tf(kf[i]);
                    Kh[row * AP + c4 + i] = xh;
                    Kl[row * AP + c4 + i] = f2tf(kf[i] - __uint_as_float(xh));
                    Vt[(c4 + i) * AP + row] = f2tf(vf[i]);
                }
            }
        }
        __syncthreads();

        // S = Q K^T (3xTF32 split)
        float s[8][4];
        #pragma unroll
        for (int nt = 0; nt < 8; nt++)
            #pragma unroll
            for (int i = 0; i < 4; i++) s[nt][i] = 0.0f;
        #pragma unroll
        for (int kg = 0; kg < 8; kg++) {
            #pragma unroll
            for (int nt = 0; nt < 8; nt++) {
                const unsigned* pk = Kh + (nt * 8 + g) * AP + kg * 8 + tg;
                const unsigned* pl = Kl + (nt * 8 + g) * AP + kg * 8 + tg;
                unsigned bh2[2] = { pk[0], pk[4] };
                unsigned bl2[2] = { pl[0], pl[4] };
                mma_tf32(s[nt], qh[kg], bh2);
                mma_tf32(s[nt], qh[kg], bl2);
                mma_tf32(s[nt], ql[kg], bh2);
            }
        }

        // bias add + tile max
        float tm0 = -INFINITY, tm1 = -INFINITY;
        #pragma unroll
        for (int nt = 0; nt < 8; nt++) {
            int col = j0 + nt * 8 + 2 * tg;
            float2 b0 = *(const float2*)(bb + (size_t)(q0 + r0) * NL + col);
            float2 b1 = *(const float2*)(bb + (size_t)(q0 + r0 + 8) * NL + col);
            s[nt][0] += b0.x; s[nt][1] += b0.y;
            s[nt][2] += b1.x; s[nt][3] += b1.y;
            tm0 = fmaxf(tm0, fmaxf(s[nt][0], s[nt][1]));
            tm1 = fmaxf(tm1, fmaxf(s[nt][2], s[nt][3]));
        }
        tm0 = fmaxf(tm0, __shfl_xor_sync(0xffffffffu, tm0, 1));
        tm0 = fmaxf(tm0, __shfl_xor_sync(0xffffffffu, tm0, 2));
        tm1 = fmaxf(tm1, __shfl_xor_sync(0xffffffffu, tm1, 1));
        tm1 = fmaxf(tm1, __shfl_xor_sync(0xffffffffu, tm1, 2));

        float mn0 = fmaxf(m0, tm0), mn1 = fmaxf(m1, tm1);
        float a0 = __expf(m0 - mn0), a1 = __expf(m1 - mn1);
        m0 = mn0; m1 = mn1;
        l0 *= a0; l1 *= a1;
        #pragma unroll
        for (int nt = 0; nt < 8; nt++) {
            o[nt][0] *= a0; o[nt][1] *= a0;
            o[nt][2] *= a1; o[nt][3] *= a1;
        }

        // p = exp(s - m); accumulate l (per-tg partial, reduced at the end);
        // stage P into smem as tf32 for the PV mma A-operand
        #pragma unroll
        for (int nt = 0; nt < 8; nt++) {
            float p0 = __expf(s[nt][0] - m0), p1 = __expf(s[nt][1] - m0);
            float p2 = __expf(s[nt][2] - m1), p3 = __expf(s[nt][3] - m1);
            l0 += p0 + p1; l1 += p2 + p3;
            unsigned* d0 = Ps + r0 * AP + nt * 8 + 2 * tg;
            unsigned* d1 = Ps + (r0 + 8) * AP + nt * 8 + 2 * tg;
            d0[0] = f2tf(p0); d0[1] = f2tf(p1);
            d1[0] = f2tf(p2); d1[1] = f2tf(p3);
        }
        __syncwarp();                  // Ps rows are warp-private

        // O += P V
        #pragma unroll
        for (int kg = 0; kg < 8; kg++) {
            const unsigned* pp = Ps + r0 * AP + kg * 8 + tg;
            const unsigned* pq = Ps + (r0 + 8) * AP + kg * 8 + tg;
            unsigned ap[4] = { pp[0], pq[0], pp[4], pq[4] };
            #pragma unroll
            for (int nt = 0; nt < 8; nt++) {
                const unsigned* pv = Vt + (nt * 8 + g) * AP + kg * 8 + tg;
                unsigned bv[2] = { pv[0], pv[4] };
                mma_tf32(o[nt], ap, bv);
            }
        }
    }

    // finish l reduction across tg and write out
    l0 += __shfl_xor_sync(0xffffffffu, l0, 1);
    l0 += __shfl_xor_sync(0xffffffffu, l0, 2);
    l1 += __shfl_xor_sync(0xffffffffu, l1, 1);
    l1 += __shfl_xor_sync(0xffffffffu, l1, 2);
    float i0 = 1.0f / l0, i1 = 1.0f / l1;

    float* op = g_ao + ((size_t)(bh >> 4) * NL + q0) * NC + h * ND;
    #pragma unroll
    for (int nt = 0; nt < 8; nt++) {
        int col = nt * 8 + 2 * tg;
        float2 r0v = make_float2(o[nt][0] * i0, o[nt][1] * i0);
        float2 r1v = make_float2(o[nt][2] * i1, o[nt][3] * i1);
        *(float2*)(op + (size_t)r0 * NC + col)       = r0v;
        *(float2*)(op + (size_t)(r0 + 8) * NC + col) = r1v;
    }
}

// ---------------- Kernel 4: output projection GEMM (TF32) + bias ------------
__global__ void __launch_bounds__(256)
k_proj(const float* __restrict__ w, const float* __restrict__ bp,
       float* __restrict__ out) {
    extern __shared__ unsigned smemu[];
    float acc[2][8][4];
    #pragma unroll
    for (int i = 0; i < 2; i++)
        #pragma unroll
        for (int j = 0; j < 8; j++)
            #pragma unroll
            for (int r = 0; r < 4; r++) acc[i][j][r] = 0.0f;

    const int n0 = blockIdx.x * 128;
    const int m0 = blockIdx.y * 128;
    gemm_tf32(g_ao, w, m0, n0, NC, smemu, acc);

    const int lane = threadIdx.x & 31, wid = threadIdx.x >> 5;
    const int wm = (wid & 3) << 5, wn = (wid >> 2) << 6;
    const int g = lane >> 2, tg = lane & 3;

    #pragma unroll
    for (int mt = 0; mt < 2; mt++) {
        #pragma unroll
        for (int half = 0; half < 2; half++) {
            int m = m0 + wm + mt * 16 + g + half * 8;
            #pragma unroll
            for (int nt = 0; nt < 8; nt++) {
                int n = n0 + wn + nt * 8 + 2 * tg;
                float2 b2 = *(const float2*)(bp + n);
                float2 r;
                r.x = acc[mt][nt][half * 2 + 0] + b2.x;
                r.y = acc[mt][nt][half * 2 + 1] + b2.y;
                *(float2*)(out + (size_t)m * NC + n) = r;
            }
        }
    }
}

// ---------------- host launcher ---------------------------------------------
extern "C" void kernel_launch(void* const* d_in, const int* in_sizes, int n_in,
                              void* d_out, int out_size) {
    const float* x         = (const float*)d_in[0];
    const float* attn_bias = (const float*)d_in[1];
    const float* w_qkv     = (const float*)d_in[2];
    const float* q_bias    = (const float*)d_in[3];
    const float* v_bias    = (const float*)d_in[4];
    const float* scale_mul = (const float*)d_in[5];
    const float* w_proj    = (const float*)d_in[6];
    const float* b_proj    = (const float*)d_in[7];
    float* out = (float*)d_out;

    const int GEMM_SMEM = 4 * SM_BUF * 4;   // 73728 B (double-buffered A+B)
    cudaFuncSetAttribute(k_qkv,  cudaFuncAttributeMaxDynamicSharedMemorySize, GEMM_SMEM);
    cudaFuncSetAttribute(k_proj, cudaFuncAttributeMaxDynamicSharedMemorySize, GEMM_SMEM);

    // QKV projection: [8192,1024] x [3072,1024]^T (TF32 tensor cores)
    k_qkv<<<dim3(24, 64), 256, GEMM_SMEM>>>(x, w_qkv, q_bias, v_bias);

    // L2-normalize q (with exp(min(scale,log100)) scale) and k
    k_norm<<<32768, 256>>>(scale_mul);

    // attention: TF32 MMA flash attention, 64-row q tiles
    const int ATTN_SMEM = 4 * 64 * AP * 4;  // 69632 B
    cudaFuncSetAttribute(k_attn, cudaFuncAttributeMaxDynamicSharedMemorySize, ATTN_SMEM);
    k_attn<<<dim3(16, 128), 128, ATTN_SMEM>>>(attn_bias);

    // output projection: [8192,1024] x [1024,1024]^T (TF32 tensor cores)
    k_proj<<<dim3(8, 64), 256, GEMM_SMEM>>>(w_proj, b_proj, out);
}